// round 10
// baseline (speedup 1.0000x reference)
#include <cuda_runtime.h>
#include <cuda_bf16.h>
#include <cstdint>

// PathRaster2d R10: zeros-first, 2048 blocks (128x16 tiles), 256 threads,
// 2 x STG.128 zeros per thread issued IMMEDIATELY (no input dependency);
// kp load + sample math + exact point-to-box prune hide under the store
// drain. Active warps (rare) recompute their 8 pixels with the full
// 32-sample min and overwrite (same thread, same address => program-ordered).
// Per-pixel arithmetic bit-identical to all passing rounds (rel_err 0.0).
//
// Measured decomposition across R1-R9: ~4us fixed launch/ramp overhead +
// ~2.7us store drain (~6.2 TB/s, near LTS cap). This probes the last
// untested grid cell (2048 blocks) for ramp-tail smoothing.

#define CANVAS_H 2048
#define CANVAS_W 2048
#define TILE_W 128
#define TILE_H 16

__global__ void __launch_bounds__(256)
path_raster_kernel(const float* __restrict__ kp, float* __restrict__ out)
{
    const int tx = threadIdx.x;          // 0..31 (lane == sample index)
    const int ty = threadIdx.y;          // 0..7
    const int x0 = blockIdx.x * TILE_W;
    const int y0 = blockIdx.y * TILE_H;

    const int x = x0 + tx * 4;
    float* base = out + (size_t)(y0 + ty) * CANVAS_W + x;   // rows ty, ty+8

    // ---- phase 1: unconditional zero stores, no input dependency ----
    const float4 z = make_float4(0.0f, 0.0f, 0.0f, 0.0f);
    *reinterpret_cast<float4*>(base) = z;
    *reinterpret_cast<float4*>(base + (size_t)8 * CANVAS_W) = z;

    // ---- phase 2: samples (hidden under store drain), ref-matched rounding ----
    // t_i = i * fl(1/31), endpoint forced to 1.0 (matches jnp.linspace)
    float t = (tx == 31) ? 1.0f : (float)tx * (1.0f / 31.0f);
    float u = __fsub_rn(1.0f, t);
    float b0 = __fmul_rn(u, u);
    float b1 = __fmul_rn(__fmul_rn(2.0f, t), u);
    float b2 = __fmul_rn(t, t);
    float ky0 = __fmul_rn(__ldg(kp + 0), 2048.0f), kx0 = __fmul_rn(__ldg(kp + 1), 2048.0f);
    float ky1 = __fmul_rn(__ldg(kp + 2), 2048.0f), kx1 = __fmul_rn(__ldg(kp + 3), 2048.0f);
    float ky2 = __fmul_rn(__ldg(kp + 4), 2048.0f), kx2 = __fmul_rn(__ldg(kp + 5), 2048.0f);
    float py = __fadd_rn(__fadd_rn(__fmul_rn(b0, ky0), __fmul_rn(b1, ky1)),
                         __fmul_rn(b2, ky2));
    float px = __fadd_rn(__fadd_rn(__fmul_rn(b0, kx0), __fmul_rn(b1, kx1)),
                         __fmul_rn(b2, kx2));

    // Exact point-to-tile-box distance; squared threshold 4.5 (> 4.0) pads for
    // rounding — only ever KEEPS extra samples (dist(pixel,s) >= boxdist(s),
    // so a sample with boxdist >= 2 can never decide a nonzero pixel here).
    float bdy = fmaxf(fmaxf((float)y0 - py, py - (float)(y0 + TILE_H - 1)), 0.0f);
    float bdx = fmaxf(fmaxf((float)x0 - px, px - (float)(x0 + TILE_W - 1)), 0.0f);
    bool near = (bdy * bdy + bdx * bdx) < 4.5f;
    unsigned mask = __ballot_sync(0xffffffffu, near);

    if (mask == 0u) return;              // 99.9% of warps: done

    // ---- phase 3 (rare): full min for this thread's 8 pixels, overwrite ----
    const float maxd = sqrtf(2048.0f * 2048.0f + 2048.0f * 2048.0f);
    const float fx0 = (float)x;
    const float fx1 = fx0 + 1.0f;
    const float fx2 = fx0 + 2.0f;
    const float fx3 = fx0 + 3.0f;
    #pragma unroll
    for (int r = 0; r < 2; r++) {
        const float fy = (float)(y0 + ty + r * 8);
        float m0 = 3.4e38f, m1 = 3.4e38f, m2 = 3.4e38f, m3 = 3.4e38f;
        unsigned mm = mask;              // warp-uniform loop
        while (mm) {
            int lane = __ffs(mm) - 1;
            mm &= mm - 1u;
            float syv = __shfl_sync(0xffffffffu, py, lane);
            float sxv = __shfl_sync(0xffffffffu, px, lane);
            float dy  = __fsub_rn(fy, syv);
            float dy2 = __fmul_rn(dy, dy);   // separate op, matches reference
            float d;
            d = __fsub_rn(fx0, sxv); m0 = fminf(m0, __fadd_rn(dy2, __fmul_rn(d, d)));
            d = __fsub_rn(fx1, sxv); m1 = fminf(m1, __fadd_rn(dy2, __fmul_rn(d, d)));
            d = __fsub_rn(fx2, sxv); m2 = fminf(m2, __fadd_rn(dy2, __fmul_rn(d, d)));
            d = __fsub_rn(fx3, sxv); m3 = fminf(m3, __fadd_rn(dy2, __fmul_rn(d, d)));
        }
        // sqrt BEFORE compare (boundary rounding identical to reference)
        float d0 = sqrtf(m0), d1 = sqrtf(m1), d2s = sqrtf(m2), d3 = sqrtf(m3);
        float4 v;
        v.x = (d0  < 2.0f) ? __fsub_rn(1.0f, __fdiv_rn(d0,  maxd)) : 0.0f;
        v.y = (d1  < 2.0f) ? __fsub_rn(1.0f, __fdiv_rn(d1,  maxd)) : 0.0f;
        v.z = (d2s < 2.0f) ? __fsub_rn(1.0f, __fdiv_rn(d2s, maxd)) : 0.0f;
        v.w = (d3  < 2.0f) ? __fsub_rn(1.0f, __fdiv_rn(d3,  maxd)) : 0.0f;
        *reinterpret_cast<float4*>(base + (size_t)(r * 8) * CANVAS_W) = v;
    }
}

extern "C" void kernel_launch(void* const* d_in, const int* in_sizes, int n_in,
                              void* d_out, int out_size)
{
    const float* kp = (const float*)d_in[0];   // [3,2] normalized (y,x)
    float* out = (float*)d_out;                // [2048,2048] fp32

    dim3 block(32, 8);
    dim3 grid(CANVAS_W / TILE_W, CANVAS_H / TILE_H);  // (16, 128) = 2048 blocks
    path_raster_kernel<<<grid, block>>>(kp, out);
}

// round 11
// speedup vs baseline: 1.0333x; 1.0333x over previous
#include <cuda_runtime.h>
#include <cuda_bf16.h>
#include <cstdint>

// PathRaster2d R11: zeros-first taken to the endpoint. 4096 blocks (128x8
// tiles), 256 threads, EXACTLY ONE STG.128 zero per thread issued immediately
// (no input dependency); kp load + per-lane sample math + exact point-to-box
// prune hide under the store drain. Active warps (rare) recompute their 4
// pixels with the full 32-sample min and overwrite (same thread, same address
// => program-ordered). Per-pixel arithmetic bit-identical to all passing
// rounds (rel_err 0.0).
//
// Measured trend R9->R10: halving per-thread store work gains ~0.5us ncu
// (6.9 -> 6.4); this is the last halving available.

#define CANVAS_H 2048
#define CANVAS_W 2048
#define TILE_W 128
#define TILE_H 8

__global__ void __launch_bounds__(256)
path_raster_kernel(const float* __restrict__ kp, float* __restrict__ out)
{
    const int tx = threadIdx.x;          // 0..31 (lane == sample index)
    const int ty = threadIdx.y;          // 0..7
    const int x0 = blockIdx.x * TILE_W;
    const int y0 = blockIdx.y * TILE_H;

    const int x = x0 + tx * 4;
    const int y = y0 + ty;
    float* base = out + (size_t)y * CANVAS_W + x;

    // ---- phase 1: one unconditional zero store, no input dependency ----
    *reinterpret_cast<float4*>(base) = make_float4(0.0f, 0.0f, 0.0f, 0.0f);

    // ---- phase 2: samples (hidden under store drain), ref-matched rounding ----
    // t_i = i * fl(1/31), endpoint forced to 1.0 (matches jnp.linspace)
    float t = (tx == 31) ? 1.0f : (float)tx * (1.0f / 31.0f);
    float u = __fsub_rn(1.0f, t);
    float b0 = __fmul_rn(u, u);
    float b1 = __fmul_rn(__fmul_rn(2.0f, t), u);
    float b2 = __fmul_rn(t, t);
    float ky0 = __fmul_rn(__ldg(kp + 0), 2048.0f), kx0 = __fmul_rn(__ldg(kp + 1), 2048.0f);
    float ky1 = __fmul_rn(__ldg(kp + 2), 2048.0f), kx1 = __fmul_rn(__ldg(kp + 3), 2048.0f);
    float ky2 = __fmul_rn(__ldg(kp + 4), 2048.0f), kx2 = __fmul_rn(__ldg(kp + 5), 2048.0f);
    float py = __fadd_rn(__fadd_rn(__fmul_rn(b0, ky0), __fmul_rn(b1, ky1)),
                         __fmul_rn(b2, ky2));
    float px = __fadd_rn(__fadd_rn(__fmul_rn(b0, kx0), __fmul_rn(b1, kx1)),
                         __fmul_rn(b2, kx2));

    // Exact point-to-tile-box distance; squared threshold 4.5 (> 4.0) pads for
    // rounding — only ever KEEPS extra samples (dist(pixel,s) >= boxdist(s),
    // so a sample with boxdist >= 2 can never decide a nonzero pixel here).
    float bdy = fmaxf(fmaxf((float)y0 - py, py - (float)(y0 + TILE_H - 1)), 0.0f);
    float bdx = fmaxf(fmaxf((float)x0 - px, px - (float)(x0 + TILE_W - 1)), 0.0f);
    bool near = (bdy * bdy + bdx * bdx) < 4.5f;
    unsigned mask = __ballot_sync(0xffffffffu, near);

    if (mask == 0u) return;              // 99.9% of warps: done

    // ---- phase 3 (rare): full min for this thread's 4 pixels, overwrite ----
    const float maxd = sqrtf(2048.0f * 2048.0f + 2048.0f * 2048.0f);
    const float fy  = (float)y;
    const float fx0 = (float)x;
    const float fx1 = fx0 + 1.0f;
    const float fx2 = fx0 + 2.0f;
    const float fx3 = fx0 + 3.0f;
    float m0 = 3.4e38f, m1 = 3.4e38f, m2 = 3.4e38f, m3 = 3.4e38f;
    unsigned mm = mask;                  // warp-uniform loop
    while (mm) {
        int lane = __ffs(mm) - 1;
        mm &= mm - 1u;
        float syv = __shfl_sync(0xffffffffu, py, lane);
        float sxv = __shfl_sync(0xffffffffu, px, lane);
        float dy  = __fsub_rn(fy, syv);
        float dy2 = __fmul_rn(dy, dy);   // separate op, matches reference
        float d;
        d = __fsub_rn(fx0, sxv); m0 = fminf(m0, __fadd_rn(dy2, __fmul_rn(d, d)));
        d = __fsub_rn(fx1, sxv); m1 = fminf(m1, __fadd_rn(dy2, __fmul_rn(d, d)));
        d = __fsub_rn(fx2, sxv); m2 = fminf(m2, __fadd_rn(dy2, __fmul_rn(d, d)));
        d = __fsub_rn(fx3, sxv); m3 = fminf(m3, __fadd_rn(dy2, __fmul_rn(d, d)));
    }
    // sqrt BEFORE compare (boundary rounding identical to reference)
    float d0 = sqrtf(m0), d1 = sqrtf(m1), d2s = sqrtf(m2), d3 = sqrtf(m3);
    float4 v;
    v.x = (d0  < 2.0f) ? __fsub_rn(1.0f, __fdiv_rn(d0,  maxd)) : 0.0f;
    v.y = (d1  < 2.0f) ? __fsub_rn(1.0f, __fdiv_rn(d1,  maxd)) : 0.0f;
    v.z = (d2s < 2.0f) ? __fsub_rn(1.0f, __fdiv_rn(d2s, maxd)) : 0.0f;
    v.w = (d3  < 2.0f) ? __fsub_rn(1.0f, __fdiv_rn(d3,  maxd)) : 0.0f;
    *reinterpret_cast<float4*>(base) = v;
}

extern "C" void kernel_launch(void* const* d_in, const int* in_sizes, int n_in,
                              void* d_out, int out_size)
{
    const float* kp = (const float*)d_in[0];   // [3,2] normalized (y,x)
    float* out = (float*)d_out;                // [2048,2048] fp32

    dim3 block(32, 8);
    dim3 grid(CANVAS_W / TILE_W, CANVAS_H / TILE_H);  // (16, 256) = 4096 blocks
    path_raster_kernel<<<grid, block>>>(kp, out);
}

// round 12
// speedup vs baseline: 1.0372x; 1.0037x over previous
#include <cuda_runtime.h>
#include <cuda_bf16.h>
#include <cstdint>

// PathRaster2d R12: R11 (4096 blocks, 1 STG.128/thread, zeros-first) + a
// 10-op control-point-bbox reject replacing the 45-instr per-warp sample
// math on the common path. Convex-hull property: every curve sample lies in
// the control-point bounding box, so a tile farther than LINE_WIDTH (+0.5
// rounding margin) from that box can contain no nonzero pixel — exact.
// Tiles inside the inflated bbox run R11's unchanged per-lane sample +
// exact per-sample box prune + full 32-sample min (rel_err 0.0).

#define CANVAS_H 2048
#define CANVAS_W 2048
#define TILE_W 128
#define TILE_H 8

__global__ void __launch_bounds__(256)
path_raster_kernel(const float* __restrict__ kp, float* __restrict__ out)
{
    const int tx = threadIdx.x;          // 0..31 (lane == sample index)
    const int ty = threadIdx.y;          // 0..7
    const int x0 = blockIdx.x * TILE_W;
    const int y0 = blockIdx.y * TILE_H;

    const int x = x0 + tx * 4;
    const int y = y0 + ty;
    float* base = out + (size_t)y * CANVAS_W + x;

    // ---- phase 1: one unconditional zero store, no input dependency ----
    *reinterpret_cast<float4*>(base) = make_float4(0.0f, 0.0f, 0.0f, 0.0f);

    // ---- phase 2: cheap exact reject via control-point bbox ----
    // (hull property: samples subset of cp bbox; margin 2.5 > 2.0 covers fp
    //  rounding and only ever keeps extra tiles)
    float2 k01 = __ldg((const float2*)kp);        // (y0n, x0n)
    float2 k23 = __ldg((const float2*)kp + 1);    // (y1n, x1n)
    float2 k45 = __ldg((const float2*)kp + 2);    // (y2n, x2n)
    float ky0 = __fmul_rn(k01.x, 2048.0f), kx0 = __fmul_rn(k01.y, 2048.0f);
    float ky1 = __fmul_rn(k23.x, 2048.0f), kx1 = __fmul_rn(k23.y, 2048.0f);
    float ky2 = __fmul_rn(k45.x, 2048.0f), kx2 = __fmul_rn(k45.y, 2048.0f);

    float ymin = fminf(fminf(ky0, ky1), ky2) - 2.5f;
    float ymax = fmaxf(fmaxf(ky0, ky1), ky2) + 2.5f;
    float xmin = fminf(fminf(kx0, kx1), kx2) - 2.5f;
    float xmax = fmaxf(fmaxf(kx0, kx1), kx2) + 2.5f;

    if ((float)(y0 + TILE_H - 1) < ymin || (float)y0 > ymax ||
        (float)(x0 + TILE_W - 1) < xmin || (float)x0 > xmax)
        return;                           // ~99% of warps exit here (~18 instrs)

    // ---- phase 3: per-lane sample (ref-matched rounding), exact box prune ----
    // t_i = i * fl(1/31), endpoint forced to 1.0 (matches jnp.linspace)
    float t = (tx == 31) ? 1.0f : (float)tx * (1.0f / 31.0f);
    float u = __fsub_rn(1.0f, t);
    float b0 = __fmul_rn(u, u);
    float b1 = __fmul_rn(__fmul_rn(2.0f, t), u);
    float b2 = __fmul_rn(t, t);
    float py = __fadd_rn(__fadd_rn(__fmul_rn(b0, ky0), __fmul_rn(b1, ky1)),
                         __fmul_rn(b2, ky2));
    float px = __fadd_rn(__fadd_rn(__fmul_rn(b0, kx0), __fmul_rn(b1, kx1)),
                         __fmul_rn(b2, kx2));

    // Exact point-to-tile-box distance; squared threshold 4.5 (> 4.0) pads for
    // rounding — only ever KEEPS extra samples (dist(pixel,s) >= boxdist(s)).
    float bdy = fmaxf(fmaxf((float)y0 - py, py - (float)(y0 + TILE_H - 1)), 0.0f);
    float bdx = fmaxf(fmaxf((float)x0 - px, px - (float)(x0 + TILE_W - 1)), 0.0f);
    bool near = (bdy * bdy + bdx * bdx) < 4.5f;
    unsigned mask = __ballot_sync(0xffffffffu, near);

    if (mask == 0u) return;

    // ---- phase 4 (rare): full min for this thread's 4 pixels, overwrite ----
    const float maxd = sqrtf(2048.0f * 2048.0f + 2048.0f * 2048.0f);
    const float fy  = (float)y;
    const float fx0 = (float)x;
    const float fx1 = fx0 + 1.0f;
    const float fx2 = fx0 + 2.0f;
    const float fx3 = fx0 + 3.0f;
    float m0 = 3.4e38f, m1 = 3.4e38f, m2 = 3.4e38f, m3 = 3.4e38f;
    unsigned mm = mask;                  // warp-uniform loop
    while (mm) {
        int lane = __ffs(mm) - 1;
        mm &= mm - 1u;
        float syv = __shfl_sync(0xffffffffu, py, lane);
        float sxv = __shfl_sync(0xffffffffu, px, lane);
        float dy  = __fsub_rn(fy, syv);
        float dy2 = __fmul_rn(dy, dy);   // separate op, matches reference
        float d;
        d = __fsub_rn(fx0, sxv); m0 = fminf(m0, __fadd_rn(dy2, __fmul_rn(d, d)));
        d = __fsub_rn(fx1, sxv); m1 = fminf(m1, __fadd_rn(dy2, __fmul_rn(d, d)));
        d = __fsub_rn(fx2, sxv); m2 = fminf(m2, __fadd_rn(dy2, __fmul_rn(d, d)));
        d = __fsub_rn(fx3, sxv); m3 = fminf(m3, __fadd_rn(dy2, __fmul_rn(d, d)));
    }
    // sqrt BEFORE compare (boundary rounding identical to reference)
    float d0 = sqrtf(m0), d1 = sqrtf(m1), d2s = sqrtf(m2), d3 = sqrtf(m3);
    float4 v;
    v.x = (d0  < 2.0f) ? __fsub_rn(1.0f, __fdiv_rn(d0,  maxd)) : 0.0f;
    v.y = (d1  < 2.0f) ? __fsub_rn(1.0f, __fdiv_rn(d1,  maxd)) : 0.0f;
    v.z = (d2s < 2.0f) ? __fsub_rn(1.0f, __fdiv_rn(d2s, maxd)) : 0.0f;
    v.w = (d3  < 2.0f) ? __fsub_rn(1.0f, __fdiv_rn(d3,  maxd)) : 0.0f;
    *reinterpret_cast<float4*>(base) = v;
}

extern "C" void kernel_launch(void* const* d_in, const int* in_sizes, int n_in,
                              void* d_out, int out_size)
{
    const float* kp = (const float*)d_in[0];   // [3,2] normalized (y,x)
    float* out = (float*)d_out;                // [2048,2048] fp32

    dim3 block(32, 8);
    dim3 grid(CANVAS_W / TILE_W, CANVAS_H / TILE_H);  // (16, 256) = 4096 blocks
    path_raster_kernel<<<grid, block>>>(kp, out);
}